// round 16
// baseline (speedup 1.0000x reference)
#include <cuda_runtime.h>
#include <cuda_bf16.h>
#include <cuda_fp16.h>
#include <cstdint>

#define MAXN 100000
#define MAXE 600000
#define NG_GRAPHS 512
#define SCAN_B 1024

// Scratch (static device globals; allocation-free).
// NOTE: g_cnt relies on (a) CUDA zero-init of device globals for the first
// call, (b) scan_add_kernel re-zeroing it at the end of every call.
__device__ __align__(16) __half g_t[MAXN * 128];   // fp16 GEMM output (gather payload)
__device__ __align__(16) __half g_h[MAXN * 128];   // fp16 activations (h2 only)
__device__ __align__(16) float g_xd[MAXN * 4];     // x * dis, padded float4
__device__ __align__(16) float g_z[MAXN * 4];      // 3-dim aggregate, padded
__device__ __align__(16) __nv_bfloat16 g_bh2[128 * 128];  // W2^T hi (n-major [n][k])
__device__ __align__(16) __nv_bfloat16 g_bl2[128 * 128];  // W2^T lo
__device__ __align__(16) __nv_bfloat16 g_bh3[64 * 128];   // W3^T hi
__device__ __align__(16) __nv_bfloat16 g_bl3[64 * 128];   // W3^T lo
__device__ __align__(16) float g_dis[MAXN];
__device__ __align__(16) int   g_cnt[MAXN];
__device__ __align__(16) int   g_offs[MAXN + 1];
__device__ __align__(16) int   g_slot[MAXE];       // within-node slot per edge
__device__ __align__(16) int   g_adj[MAXE];
__device__ __align__(16) int   g_bsum[128];
__device__ __align__(16) float g_sums[NG_GRAPHS * 64];
__device__ __align__(16) float g_gcnt[NG_GRAPHS];

// ---------------------------------------------------------------------------
// count in-degrees, 1 edge/thread (max parallelism hides ATOMG latency);
// atomic return value IS the slot. Also zeroes pooling buffers.
// ---------------------------------------------------------------------------
__global__ void count_kernel(const int* __restrict__ dst, int* cnt, int* slot,
                             float* sums, float* gcnt, int E) {
    int i = blockIdx.x * blockDim.x + threadIdx.x;
    if (i < E) slot[i] = atomicAdd(&cnt[dst[i]], 1);
    if (i < NG_GRAPHS * 64) sums[i] = 0.f;
    if (i < NG_GRAPHS) gcnt[i] = 0.f;
}

// ---------------------------------------------------------------------------
// tile scan: warp-shfl inclusive scan, 2 barriers (vs 20 in naive ladder)
// ---------------------------------------------------------------------------
__global__ __launch_bounds__(SCAN_B) void scan_block_kernel(
    const int* __restrict__ cnt, int* offs, int* bsum, int N) {
    __shared__ int wsum[32];
    int t = threadIdx.x;
    int warp = t >> 5;
    int lane = t & 31;
    int i = blockIdx.x * SCAN_B + t;
    int v = (i < N) ? cnt[i] : 0;
    // inclusive scan within warp
    int s = v;
#pragma unroll
    for (int o = 1; o < 32; o <<= 1) {
        int n = __shfl_up_sync(0xFFFFFFFFu, s, o);
        if (lane >= o) s += n;
    }
    if (lane == 31) wsum[warp] = s;
    __syncthreads();
    if (warp == 0) {
        int w = wsum[lane];
#pragma unroll
        for (int o = 1; o < 32; o <<= 1) {
            int n = __shfl_up_sync(0xFFFFFFFFu, w, o);
            if (lane >= o) w += n;
        }
        wsum[lane] = w;  // inclusive warp-total prefix
    }
    __syncthreads();
    int base = (warp > 0) ? wsum[warp - 1] : 0;
    int incl = s + base;
    if (i < N) offs[i] = incl - v;  // exclusive within tile
    if (t == SCAN_B - 1) bsum[blockIdx.x] = incl;  // tile total
}

// apply top-level scan (computed in-block over <=98 tile totals), finalize
// offs, compute dis and xd = x*dis, and self-clear cnt for the next call.
__global__ __launch_bounds__(256) void scan_add_kernel(
    int* offs, const int* __restrict__ bsum, int* cnt,
    const float* __restrict__ x, float* dis, float* xd, int N, int E) {
    __shared__ int base_sh;
    int tile = blockIdx.x >> 2;  // 256-thread block lies inside one 1024 tile
    if (threadIdx.x < 32) {
        int s = 0;
        for (int j = threadIdx.x; j < tile; j += 32) s += bsum[j];
#pragma unroll
        for (int o = 16; o; o >>= 1) s += __shfl_down_sync(0xFFFFFFFFu, s, o);
        if (threadIdx.x == 0) base_sh = s;
    }
    __syncthreads();
    int i = blockIdx.x * 256 + threadIdx.x;
    if (i < N) {
        offs[i] += base_sh;
        float d = rsqrtf((float)cnt[i] + 1.0f);  // +1 self loop
        cnt[i] = 0;                              // reset for next call
        dis[i] = d;
        float4 v;
        v.x = x[i * 3 + 0] * d;
        v.y = x[i * 3 + 1] * d;
        v.z = x[i * 3 + 2] * d;
        v.w = 0.f;
        *(float4*)(xd + i * 4) = v;
    }
    if (i == 0) offs[N] = E;
}

// ---------------------------------------------------------------------------
// fused: CSR fill (atomic-free scatter, 1 edge/thread) + W2/W3 prep
// ---------------------------------------------------------------------------
__global__ void fill_prep_kernel(const int* __restrict__ src, const int* __restrict__ dst,
                                 const int* __restrict__ offs, const int* __restrict__ slot,
                                 int* adj, int E,
                                 const float* __restrict__ W2, const float* __restrict__ W3,
                                 __nv_bfloat16* bh2, __nv_bfloat16* bl2,
                                 __nv_bfloat16* bh3, __nv_bfloat16* bl3) {
    int i = blockIdx.x * blockDim.x + threadIdx.x;
    if (i < E) {
        adj[__ldg(&offs[dst[i]]) + slot[i]] = src[i];
        return;
    }
    int k = i - E;
    if (k < 128 * 128) {
        int kk = k >> 7, n = k & 127;            // coalesced read of W2 row kk
        float w = W2[kk * 128 + n];
        __nv_bfloat16 hi = __float2bfloat16_rn(w);
        __nv_bfloat16 lo = __float2bfloat16_rn(w - __bfloat162float(hi));
        bh2[n * 128 + kk] = hi;                  // scattered store
        bl2[n * 128 + kk] = lo;
    } else if (k < 128 * 128 + 64 * 128) {
        int j = k - 128 * 128;
        int kk = j >> 6, n = j & 63;             // coalesced read of W3 row kk
        float w = W3[kk * 64 + n];
        __nv_bfloat16 hi = __float2bfloat16_rn(w);
        __nv_bfloat16 lo = __float2bfloat16_rn(w - __bfloat162float(hi));
        bh3[n * 128 + kk] = hi;
        bl3[n * 128 + kk] = lo;
    }
}

// ---------------------------------------------------------------------------
// layer-1 aggregation in 3-dim space: z[d] = xd[d] + sum_{s in adj(d)} xd[s]
// One THREAD per node (avg degree ~6 -> no idle lanes), unroll 4 (MLP).
// ---------------------------------------------------------------------------
__global__ __launch_bounds__(256) void agg3_kernel(
    const int* __restrict__ offs, const int* __restrict__ adj,
    const float* __restrict__ xd, float* __restrict__ z, int N) {
    int i = blockIdx.x * blockDim.x + threadIdx.x;
    if (i >= N) return;
    int beg = offs[i];
    int end = offs[i + 1];
    const float4* xv = (const float4*)xd;
    float4 s = __ldg(&xv[i]);  // self loop
    float sx = s.x, sy = s.y, sz = s.z;
    float ux = 0.f, uy = 0.f, uz = 0.f;
    int e = beg;
    for (; e + 4 <= end; e += 4) {
        int a0 = __ldg(&adj[e]);
        int a1 = __ldg(&adj[e + 1]);
        int a2 = __ldg(&adj[e + 2]);
        int a3 = __ldg(&adj[e + 3]);
        float4 v0 = __ldg(&xv[a0]);
        float4 v1 = __ldg(&xv[a1]);
        float4 v2 = __ldg(&xv[a2]);
        float4 v3 = __ldg(&xv[a3]);
        sx += v0.x + v2.x; sy += v0.y + v2.y; sz += v0.z + v2.z;
        ux += v1.x + v3.x; uy += v1.y + v3.y; uz += v1.z + v3.z;
    }
    for (; e < end; e++) {
        int a = __ldg(&adj[e]);
        float4 v = __ldg(&xv[a]);
        sx += v.x; sy += v.y; sz += v.z;
    }
    float4 o = make_float4(sx + ux, sy + uy, sz + uz, 0.f);
    *(float4*)(z + i * 4) = o;
}

#define LDH 72  // halfs per smem row (64 + 8 pad)

// ---------------------------------------------------------------------------
// FUSED layer-1 transform + layer-2 GEMM (tensor cores):
//   h1[n][c] = relu(dis[n]*(z[n]@W1[:,c]) + b1[c])  computed in A-staging,
//   out[n]   = fp16( (h1[n] @ W2) * dis[n] ),  bf16x3 split, fp32 accum.
// W1/b1 packed as float4 (w0,w1,w2,b) -> 1 LDS128 per staged element.
// ---------------------------------------------------------------------------
__global__ __launch_bounds__(256) void gemm_l2_kernel(
    const float* __restrict__ z, const float* __restrict__ W1,
    const float* __restrict__ b1, const __nv_bfloat16* __restrict__ Bhg,
    const __nv_bfloat16* __restrict__ Blg, const float* __restrict__ dis,
    __half* __restrict__ out, int N) {
    extern __shared__ __align__(16) __nv_bfloat16 smh[];
    __nv_bfloat16* Ah = smh;             // 128 x LDH
    __nv_bfloat16* Al = Ah + 128 * LDH;  // 128 x LDH
    __nv_bfloat16* Bh = Al + 128 * LDH;  // 128 x LDH
    __nv_bfloat16* Bl = Bh + 128 * LDH;  // 128 x LDH
    __shared__ float4 wb4[128];          // (W1[0][c], W1[1][c], W1[2][c], b1[c])

    const int tid = threadIdx.x;
    const int warp = tid >> 5;
    const int lane = tid & 31;
    const int g = lane >> 2;
    const int tg = lane & 3;
    const int n0 = blockIdx.x * 128;

    if (tid < 128)
        wb4[tid] = make_float4(W1[tid], W1[128 + tid], W1[256 + tid], b1[tid]);

    float acc[16][4];
#pragma unroll
    for (int i = 0; i < 16; i++) {
        acc[i][0] = acc[i][1] = acc[i][2] = acc[i][3] = 0.f;
    }

    for (int kc = 0; kc < 128; kc += 64) {
        __syncthreads();  // wb4 ready (first iter); smem reuse (later iters)
        // stage A chunk [128 x 64]: h1 computed on the fly, bf16 hi/lo split
        for (int i = tid; i < 128 * 8; i += 256) {
            int r = i >> 3, c8 = i & 7;          // 8 cols per thread-iter
            int n = n0 + r;
            uint4 hu = make_uint4(0u, 0u, 0u, 0u);
            uint4 lu = make_uint4(0u, 0u, 0u, 0u);
            if (n < N) {
                float4 zv = *(const float4*)(z + n * 4);
                float d = dis[n];
                uint32_t* hw = (uint32_t*)&hu;
                uint32_t* lw = (uint32_t*)&lu;
#pragma unroll
                for (int q = 0; q < 4; q++) {
                    int c0 = kc + c8 * 8 + q * 2;
                    float4 wa = wb4[c0];
                    float4 wbv = wb4[c0 + 1];
                    float o0 = fmaxf(fmaf(zv.x * wa.x + zv.y * wa.y + zv.z * wa.z, d, wa.w), 0.f);
                    float o1 = fmaxf(fmaf(zv.x * wbv.x + zv.y * wbv.y + zv.z * wbv.z, d, wbv.w), 0.f);
                    __nv_bfloat16 h0 = __float2bfloat16_rn(o0);
                    __nv_bfloat16 h1 = __float2bfloat16_rn(o1);
                    __nv_bfloat162 hh = {h0, h1};
                    __nv_bfloat162 ll = {__float2bfloat16_rn(o0 - __bfloat162float(h0)),
                                         __float2bfloat16_rn(o1 - __bfloat162float(h1))};
                    hw[q] = *(uint32_t*)&hh;
                    lw[q] = *(uint32_t*)&ll;
                }
            }
            *(uint4*)(Ah + r * LDH + c8 * 8) = hu;
            *(uint4*)(Al + r * LDH + c8 * 8) = lu;
        }
        // stage B chunk [128 x 64]
        for (int i = tid; i < 128 * 8; i += 256) {
            int r = i >> 3, c8 = i & 7;
            *(uint4*)(Bh + r * LDH + c8 * 8) = *(const uint4*)(Bhg + r * 128 + kc + c8 * 8);
            *(uint4*)(Bl + r * LDH + c8 * 8) = *(const uint4*)(Blg + r * 128 + kc + c8 * 8);
        }
        __syncthreads();

        const __nv_bfloat16* ar0 = Ah + (warp * 16 + g) * LDH + 2 * tg;
        const __nv_bfloat16* al0 = Al + (warp * 16 + g) * LDH + 2 * tg;
#pragma unroll
        for (int ks = 0; ks < 4; ks++) {
            const int ko = ks * 16;
            uint32_t ah0 = *(const uint32_t*)(ar0 + ko);
            uint32_t ah1 = *(const uint32_t*)(ar0 + 8 * LDH + ko);
            uint32_t ah2 = *(const uint32_t*)(ar0 + ko + 8);
            uint32_t ah3 = *(const uint32_t*)(ar0 + 8 * LDH + ko + 8);
            uint32_t aw0 = *(const uint32_t*)(al0 + ko);
            uint32_t aw1 = *(const uint32_t*)(al0 + 8 * LDH + ko);
            uint32_t aw2 = *(const uint32_t*)(al0 + ko + 8);
            uint32_t aw3 = *(const uint32_t*)(al0 + 8 * LDH + ko + 8);
#pragma unroll
            for (int nt = 0; nt < 16; nt++) {
                const __nv_bfloat16* bhr = Bh + (nt * 8 + g) * LDH + 2 * tg + ko;
                const __nv_bfloat16* blr = Bl + (nt * 8 + g) * LDH + 2 * tg + ko;
                uint32_t bh0 = *(const uint32_t*)bhr;
                uint32_t bh1 = *(const uint32_t*)(bhr + 8);
                uint32_t bl0 = *(const uint32_t*)blr;
                uint32_t bl1 = *(const uint32_t*)(blr + 8);
                asm volatile(
                    "mma.sync.aligned.m16n8k16.row.col.f32.bf16.bf16.f32 "
                    "{%0,%1,%2,%3}, {%4,%5,%6,%7}, {%8,%9}, {%0,%1,%2,%3};"
                    : "+f"(acc[nt][0]), "+f"(acc[nt][1]), "+f"(acc[nt][2]), "+f"(acc[nt][3])
                    : "r"(ah0), "r"(ah1), "r"(ah2), "r"(ah3), "r"(bh0), "r"(bh1));
                asm volatile(
                    "mma.sync.aligned.m16n8k16.row.col.f32.bf16.bf16.f32 "
                    "{%0,%1,%2,%3}, {%4,%5,%6,%7}, {%8,%9}, {%0,%1,%2,%3};"
                    : "+f"(acc[nt][0]), "+f"(acc[nt][1]), "+f"(acc[nt][2]), "+f"(acc[nt][3])
                    : "r"(aw0), "r"(aw1), "r"(aw2), "r"(aw3), "r"(bh0), "r"(bh1));
                asm volatile(
                    "mma.sync.aligned.m16n8k16.row.col.f32.bf16.bf16.f32 "
                    "{%0,%1,%2,%3}, {%4,%5,%6,%7}, {%8,%9}, {%0,%1,%2,%3};"
                    : "+f"(acc[nt][0]), "+f"(acc[nt][1]), "+f"(acc[nt][2]), "+f"(acc[nt][3])
                    : "r"(ah0), "r"(ah1), "r"(ah2), "r"(ah3), "r"(bl0), "r"(bl1));
            }
        }
    }

    int m0 = n0 + warp * 16 + g;
    int m1 = m0 + 8;
    float d0 = (m0 < N) ? dis[m0] : 0.f;
    float d1 = (m1 < N) ? dis[m1] : 0.f;
#pragma unroll
    for (int nt = 0; nt < 16; nt++) {
        if (m0 < N) {
            __half2 o = __floats2half2_rn(acc[nt][0] * d0, acc[nt][1] * d0);
            *(__half2*)(out + (size_t)m0 * 128 + nt * 8 + tg * 2) = o;
        }
        if (m1 < N) {
            __half2 o = __floats2half2_rn(acc[nt][2] * d1, acc[nt][3] * d1);
            *(__half2*)(out + (size_t)m1 * 128 + nt * 8 + tg * 2) = o;
        }
    }
}

// ---------------------------------------------------------------------------
// bf16x3 tensor-core GEMM (layer 3): A = fp16 h, F = 64.
// ---------------------------------------------------------------------------
template <int F>
__global__ __launch_bounds__(256) void gemm_mma_kernel(
    const __half* __restrict__ A, const __nv_bfloat16* __restrict__ Bhg,
    const __nv_bfloat16* __restrict__ Blg, const float* __restrict__ dis,
    __half* __restrict__ out, int N) {
    extern __shared__ __align__(16) __nv_bfloat16 smh[];
    __nv_bfloat16* Ah = smh;             // 128 x LDH
    __nv_bfloat16* Al = Ah + 128 * LDH;  // 128 x LDH
    __nv_bfloat16* Bh = Al + 128 * LDH;  // F x LDH
    __nv_bfloat16* Bl = Bh + F * LDH;    // F x LDH

    const int tid = threadIdx.x;
    const int warp = tid >> 5;
    const int lane = tid & 31;
    const int g = lane >> 2;
    const int tg = lane & 3;
    const int n0 = blockIdx.x * 128;

    constexpr int NT = F / 8;
    float acc[NT][4];
#pragma unroll
    for (int i = 0; i < NT; i++) {
        acc[i][0] = acc[i][1] = acc[i][2] = acc[i][3] = 0.f;
    }

    for (int kc = 0; kc < 128; kc += 64) {
        __syncthreads();
        for (int i = tid; i < 128 * 8; i += 256) {
            int r = i >> 3, c8 = i & 7;
            uint4 raw = make_uint4(0u, 0u, 0u, 0u);
            int n = n0 + r;
            if (n < N) raw = *(const uint4*)(A + (size_t)n * 128 + kc + c8 * 8);
            const __half2* hp = (const __half2*)&raw;
            uint4 hu, lu;
            uint32_t* hw = (uint32_t*)&hu;
            uint32_t* lw = (uint32_t*)&lu;
#pragma unroll
            for (int q = 0; q < 4; q++) {
                float2 fv = __half22float2(hp[q]);
                __nv_bfloat16 h0 = __float2bfloat16_rn(fv.x);
                __nv_bfloat16 h1 = __float2bfloat16_rn(fv.y);
                __nv_bfloat162 hh = {h0, h1};
                __nv_bfloat162 ll = {__float2bfloat16_rn(fv.x - __bfloat162float(h0)),
                                     __float2bfloat16_rn(fv.y - __bfloat162float(h1))};
                hw[q] = *(uint32_t*)&hh;
                lw[q] = *(uint32_t*)&ll;
            }
            *(uint4*)(Ah + r * LDH + c8 * 8) = hu;
            *(uint4*)(Al + r * LDH + c8 * 8) = lu;
        }
        for (int i = tid; i < F * 8; i += 256) {
            int r = i >> 3, c8 = i & 7;
            *(uint4*)(Bh + r * LDH + c8 * 8) = *(const uint4*)(Bhg + r * 128 + kc + c8 * 8);
            *(uint4*)(Bl + r * LDH + c8 * 8) = *(const uint4*)(Blg + r * 128 + kc + c8 * 8);
        }
        __syncthreads();

        const __nv_bfloat16* ar0 = Ah + (warp * 16 + g) * LDH + 2 * tg;
        const __nv_bfloat16* al0 = Al + (warp * 16 + g) * LDH + 2 * tg;
#pragma unroll
        for (int ks = 0; ks < 4; ks++) {
            const int ko = ks * 16;
            uint32_t ah0 = *(const uint32_t*)(ar0 + ko);
            uint32_t ah1 = *(const uint32_t*)(ar0 + 8 * LDH + ko);
            uint32_t ah2 = *(const uint32_t*)(ar0 + ko + 8);
            uint32_t ah3 = *(const uint32_t*)(ar0 + 8 * LDH + ko + 8);
            uint32_t aw0 = *(const uint32_t*)(al0 + ko);
            uint32_t aw1 = *(const uint32_t*)(al0 + 8 * LDH + ko);
            uint32_t aw2 = *(const uint32_t*)(al0 + ko + 8);
            uint32_t aw3 = *(const uint32_t*)(al0 + 8 * LDH + ko + 8);
#pragma unroll
            for (int nt = 0; nt < NT; nt++) {
                const __nv_bfloat16* bhr = Bh + (nt * 8 + g) * LDH + 2 * tg + ko;
                const __nv_bfloat16* blr = Bl + (nt * 8 + g) * LDH + 2 * tg + ko;
                uint32_t bh0 = *(const uint32_t*)bhr;
                uint32_t bh1 = *(const uint32_t*)(bhr + 8);
                uint32_t bl0 = *(const uint32_t*)blr;
                uint32_t bl1 = *(const uint32_t*)(blr + 8);
                asm volatile(
                    "mma.sync.aligned.m16n8k16.row.col.f32.bf16.bf16.f32 "
                    "{%0,%1,%2,%3}, {%4,%5,%6,%7}, {%8,%9}, {%0,%1,%2,%3};"
                    : "+f"(acc[nt][0]), "+f"(acc[nt][1]), "+f"(acc[nt][2]), "+f"(acc[nt][3])
                    : "r"(ah0), "r"(ah1), "r"(ah2), "r"(ah3), "r"(bh0), "r"(bh1));
                asm volatile(
                    "mma.sync.aligned.m16n8k16.row.col.f32.bf16.bf16.f32 "
                    "{%0,%1,%2,%3}, {%4,%5,%6,%7}, {%8,%9}, {%0,%1,%2,%3};"
                    : "+f"(acc[nt][0]), "+f"(acc[nt][1]), "+f"(acc[nt][2]), "+f"(acc[nt][3])
                    : "r"(aw0), "r"(aw1), "r"(aw2), "r"(aw3), "r"(bh0), "r"(bh1));
                asm volatile(
                    "mma.sync.aligned.m16n8k16.row.col.f32.bf16.bf16.f32 "
                    "{%0,%1,%2,%3}, {%4,%5,%6,%7}, {%8,%9}, {%0,%1,%2,%3};"
                    : "+f"(acc[nt][0]), "+f"(acc[nt][1]), "+f"(acc[nt][2]), "+f"(acc[nt][3])
                    : "r"(ah0), "r"(ah1), "r"(ah2), "r"(ah3), "r"(bl0), "r"(bl1));
            }
        }
    }

    int m0 = n0 + warp * 16 + g;
    int m1 = m0 + 8;
    float d0 = (m0 < N) ? dis[m0] : 0.f;
    float d1 = (m1 < N) ? dis[m1] : 0.f;
#pragma unroll
    for (int nt = 0; nt < NT; nt++) {
        if (m0 < N) {
            __half2 o = __floats2half2_rn(acc[nt][0] * d0, acc[nt][1] * d0);
            *(__half2*)(out + (size_t)m0 * F + nt * 8 + tg * 2) = o;
        }
        if (m1 < N) {
            __half2 o = __floats2half2_rn(acc[nt][2] * d1, acc[nt][3] * d1);
            *(__half2*)(out + (size_t)m1 * F + nt * 8 + tg * 2) = o;
        }
    }
}

// ---------------------------------------------------------------------------
// CSR gather + epilogue: h[d] = fp16(relu(dis[d]*(sum t[s] + t[d]) + b))
// One warp per dst node; fp16 payload, fp32 accumulation, fp16 h out.
// ---------------------------------------------------------------------------
template <int F>
__global__ __launch_bounds__(256) void gather_kernel(
    const int* __restrict__ offs, const int* __restrict__ adj,
    const __half* __restrict__ t, const float* __restrict__ dis,
    const float* __restrict__ b, __half* __restrict__ h, int N) {
    int node = (blockIdx.x * 256 + threadIdx.x) >> 5;
    int lane = threadIdx.x & 31;
    if (node >= N) return;
    int beg = offs[node];
    int end = offs[node + 1];
    float d = dis[node];
    if constexpr (F == 128) {
        const uint2* tv = (const uint2*)t;
        uint2 raw = __ldg(&tv[(size_t)node * 32 + lane]);  // self loop
        float2 f0 = __half22float2(*(__half2*)&raw.x);
        float2 f1 = __half22float2(*(__half2*)&raw.y);
        float s0 = f0.x, s1 = f0.y, s2 = f1.x, s3 = f1.y;
        float u0 = 0.f, u1 = 0.f, u2 = 0.f, u3 = 0.f;
        int e = beg;
        for (; e + 4 <= end; e += 4) {
            int a0 = __ldg(&adj[e]);
            int a1 = __ldg(&adj[e + 1]);
            int a2 = __ldg(&adj[e + 2]);
            int a3 = __ldg(&adj[e + 3]);
            uint2 r0 = __ldg(&tv[(size_t)a0 * 32 + lane]);
            uint2 r1 = __ldg(&tv[(size_t)a1 * 32 + lane]);
            uint2 r2 = __ldg(&tv[(size_t)a2 * 32 + lane]);
            uint2 r3 = __ldg(&tv[(size_t)a3 * 32 + lane]);
            float2 x0 = __half22float2(*(__half2*)&r0.x);
            float2 x1 = __half22float2(*(__half2*)&r0.y);
            float2 y0 = __half22float2(*(__half2*)&r1.x);
            float2 y1 = __half22float2(*(__half2*)&r1.y);
            float2 z0 = __half22float2(*(__half2*)&r2.x);
            float2 z1 = __half22float2(*(__half2*)&r2.y);
            float2 w0 = __half22float2(*(__half2*)&r3.x);
            float2 w1 = __half22float2(*(__half2*)&r3.y);
            s0 += x0.x + z0.x; s1 += x0.y + z0.y;
            s2 += x1.x + z1.x; s3 += x1.y + z1.y;
            u0 += y0.x + w0.x; u1 += y0.y + w0.y;
            u2 += y1.x + w1.x; u3 += y1.y + w1.y;
        }
        for (; e < end; e++) {
            int a = __ldg(&adj[e]);
            uint2 r0 = __ldg(&tv[(size_t)a * 32 + lane]);
            float2 x0 = __half22float2(*(__half2*)&r0.x);
            float2 x1 = __half22float2(*(__half2*)&r0.y);
            s0 += x0.x; s1 += x0.y; s2 += x1.x; s3 += x1.y;
        }
        float4 bv = __ldg(&((const float4*)b)[lane]);
        float o0 = fmaxf(fmaf(s0 + u0, d, bv.x), 0.f);
        float o1 = fmaxf(fmaf(s1 + u1, d, bv.y), 0.f);
        float o2 = fmaxf(fmaf(s2 + u2, d, bv.z), 0.f);
        float o3 = fmaxf(fmaf(s3 + u3, d, bv.w), 0.f);
        __half2 q0 = __floats2half2_rn(o0, o1);
        __half2 q1 = __floats2half2_rn(o2, o3);
        uint2 pk;
        pk.x = *(unsigned*)&q0;
        pk.y = *(unsigned*)&q1;
        ((uint2*)h)[(size_t)node * 32 + lane] = pk;
    } else {
        const uint32_t* tv = (const uint32_t*)t;
        uint32_t raw = __ldg(&tv[(size_t)node * 32 + lane]);  // self loop
        float2 f0 = __half22float2(*(__half2*)&raw);
        float s0 = f0.x, s1 = f0.y;
        float u0 = 0.f, u1 = 0.f;
        int e = beg;
        for (; e + 4 <= end; e += 4) {
            int a0 = __ldg(&adj[e]);
            int a1 = __ldg(&adj[e + 1]);
            int a2 = __ldg(&adj[e + 2]);
            int a3 = __ldg(&adj[e + 3]);
            uint32_t r0 = __ldg(&tv[(size_t)a0 * 32 + lane]);
            uint32_t r1 = __ldg(&tv[(size_t)a1 * 32 + lane]);
            uint32_t r2 = __ldg(&tv[(size_t)a2 * 32 + lane]);
            uint32_t r3 = __ldg(&tv[(size_t)a3 * 32 + lane]);
            float2 x0 = __half22float2(*(__half2*)&r0);
            float2 y0 = __half22float2(*(__half2*)&r1);
            float2 z0 = __half22float2(*(__half2*)&r2);
            float2 w0 = __half22float2(*(__half2*)&r3);
            s0 += x0.x + z0.x; s1 += x0.y + z0.y;
            u0 += y0.x + w0.x; u1 += y0.y + w0.y;
        }
        for (; e < end; e++) {
            int a = __ldg(&adj[e]);
            uint32_t r0 = __ldg(&tv[(size_t)a * 32 + lane]);
            float2 x0 = __half22float2(*(__half2*)&r0);
            s0 += x0.x; s1 += x0.y;
        }
        float2 bv = __ldg(&((const float2*)b)[lane]);
        float o0 = fmaxf(fmaf(s0 + u0, d, bv.x), 0.f);
        float o1 = fmaxf(fmaf(s1 + u1, d, bv.y), 0.f);
        __half2 q = __floats2half2_rn(o0, o1);
        ((uint32_t*)h)[(size_t)node * 32 + lane] = *(unsigned*)&q;
    }
}

// ---------------------------------------------------------------------------
// pooling: batch sorted -> segmented reduction. Block = 256 thr = 4 groups of
// 64 features; each group reduces a 64-node segment. fp16 h in, fp32 accum.
// ---------------------------------------------------------------------------
__global__ __launch_bounds__(256) void pool_kernel(
    const __half* __restrict__ h, const int* __restrict__ batch,
    float* __restrict__ sums, float* __restrict__ cnt, int N) {
    int grp = threadIdx.x >> 6;
    int f = threadIdx.x & 63;
    int start = blockIdx.x * 256 + grp * 64;
    if (start >= N) return;
    int end = min(start + 64, N);
    int g = batch[start];
    float s = 0.f, c = 0.f;
    for (int n = start; n < end; n++) {
        int bn = batch[n];
        if (bn != g) {
            atomicAdd(&sums[g * 64 + f], s);
            if (f == 0) atomicAdd(&cnt[g], c);
            s = 0.f; c = 0.f; g = bn;
        }
        s += __half2float(h[(size_t)n * 64 + f]);
        c += 1.f;
    }
    atomicAdd(&sums[g * 64 + f], s);
    if (f == 0) atomicAdd(&cnt[g], c);
}

__global__ void final_kernel(const float* __restrict__ sums, const float* __restrict__ cnt,
                             const float* __restrict__ Wl, const float* __restrict__ bl,
                             float* __restrict__ out) {
    int g = blockIdx.x * blockDim.x + threadIdx.x;
    if (g >= NG_GRAPHS) return;
    float c = fmaxf(cnt[g], 1.0f);
    float acc = 0.f;
#pragma unroll
    for (int f = 0; f < 64; f++) acc = fmaf(sums[g * 64 + f], Wl[f], acc);
    out[g] = acc / c + bl[0];
}

// ---------------------------------------------------------------------------
extern "C" void kernel_launch(void* const* d_in, const int* in_sizes, int n_in,
                              void* d_out, int out_size) {
    const float* x     = (const float*)d_in[0];
    const int*   ei    = (const int*)d_in[1];    // int32
    const int*   batch = (const int*)d_in[2];    // int32
    const float* W1 = (const float*)d_in[3];
    const float* b1 = (const float*)d_in[4];
    const float* W2 = (const float*)d_in[5];
    const float* b2 = (const float*)d_in[6];
    const float* W3 = (const float*)d_in[7];
    const float* b3 = (const float*)d_in[8];
    const float* Wl = (const float*)d_in[9];
    const float* bl = (const float*)d_in[10];
    float* out = (float*)d_out;

    const int N = in_sizes[0] / 3;
    const int E = in_sizes[1] / 2;
    const int* srcp = ei;
    const int* dstp = ei + E;

    float *xd, *z, *dis, *sums, *gcnt;
    __half *t, *h;
    __nv_bfloat16 *bh2, *bl2, *bh3, *bl3;
    int *cnt, *offs, *slot, *adj, *bsum;
    cudaGetSymbolAddress((void**)&t, g_t);
    cudaGetSymbolAddress((void**)&h, g_h);
    cudaGetSymbolAddress((void**)&xd, g_xd);
    cudaGetSymbolAddress((void**)&z, g_z);
    cudaGetSymbolAddress((void**)&bh2, g_bh2);
    cudaGetSymbolAddress((void**)&bl2, g_bl2);
    cudaGetSymbolAddress((void**)&bh3, g_bh3);
    cudaGetSymbolAddress((void**)&bl3, g_bl3);
    cudaGetSymbolAddress((void**)&dis, g_dis);
    cudaGetSymbolAddress((void**)&cnt, g_cnt);
    cudaGetSymbolAddress((void**)&offs, g_offs);
    cudaGetSymbolAddress((void**)&slot, g_slot);
    cudaGetSymbolAddress((void**)&adj, g_adj);
    cudaGetSymbolAddress((void**)&bsum, g_bsum);
    cudaGetSymbolAddress((void**)&sums, g_sums);
    cudaGetSymbolAddress((void**)&gcnt, g_gcnt);

    const int SMEM128 = (2 * 128 + 2 * 128) * LDH * 2;  // 73,728 B
    const int SMEM64  = (2 * 128 + 2 * 64) * LDH * 2;   // 55,296 B
    cudaFuncSetAttribute(gemm_l2_kernel,
                         cudaFuncAttributeMaxDynamicSharedMemorySize, SMEM128);
    cudaFuncSetAttribute(gemm_mma_kernel<64>,
                         cudaFuncAttributeMaxDynamicSharedMemorySize, SMEM64);

    const int nB = (N + 255) / 256;
    const int eB = (E + 255) / 256;
    const int NB_SCAN = (N + SCAN_B - 1) / SCAN_B;
    const int wB = (N * 32 + 255) / 256;      // warp-per-node grids
    const int gB = (N + 127) / 128;           // gemm grids
    const int fpB = (E + 128 * 128 + 64 * 128 + 255) / 256;

    // --- CSR build + prep (cnt zero at entry: zero-init call 1, ---
    // --- self-cleared by scan_add every call)                   ---
    count_kernel<<<eB, 256>>>(dstp, cnt, slot, sums, gcnt, E);
    scan_block_kernel<<<NB_SCAN, SCAN_B>>>(cnt, offs, bsum, N);
    scan_add_kernel<<<nB, 256>>>(offs, bsum, cnt, x, dis, xd, N, E);
    fill_prep_kernel<<<fpB, 256>>>(srcp, dstp, offs, slot, adj, E,
                                   W2, W3, bh2, bl2, bh3, bl3);

    // --- layer 1 aggregate (3-dim) ---
    agg3_kernel<<<nB, 256>>>(offs, adj, xd, z, N);

    // --- fused layer-1 transform + layer-2 GEMM ---
    gemm_l2_kernel<<<gB, 256, SMEM128>>>(z, W1, b1, bh2, bl2, dis, t, N);
    gather_kernel<128><<<wB, 256>>>(offs, adj, t, dis, b2, h, N);

    // --- layer 3 (128 -> 64) ---
    gemm_mma_kernel<64><<<gB, 256, SMEM64>>>(h, bh3, bl3, dis, t, N);
    gather_kernel<64><<<wB, 256>>>(offs, adj, t, dis, b3, h, N);

    // --- pooling + final linear ---
    pool_kernel<<<nB, 256>>>(h, batch, sums, gcnt, N);
    final_kernel<<<2, 256>>>(sums, gcnt, Wl, bl, out);
}

// round 17
// speedup vs baseline: 1.2315x; 1.2315x over previous
#include <cuda_runtime.h>
#include <cuda_bf16.h>
#include <cuda_fp16.h>
#include <cstdint>

#define MAXN 100000
#define MAXE 600000
#define NG_GRAPHS 512
#define SCAN_B 1024

// Scratch (static device globals; allocation-free).
// NOTE: g_cnt relies on (a) CUDA zero-init of device globals for the first
// call, (b) scan_add_kernel re-zeroing it at the end of every call.
__device__ __align__(16) __half g_t[MAXN * 128];   // fp16 GEMM output (gather payload)
__device__ __align__(16) __half g_h[MAXN * 128];   // fp16 activations (h2 only)
__device__ __align__(16) float g_xd[MAXN * 4];     // x * dis, padded float4
__device__ __align__(16) float g_z[MAXN * 4];      // 3-dim aggregate, padded
__device__ __align__(16) __nv_bfloat16 g_bh2[128 * 128];  // W2^T hi (n-major [n][k])
__device__ __align__(16) __nv_bfloat16 g_bl2[128 * 128];  // W2^T lo
__device__ __align__(16) __nv_bfloat16 g_bh3[64 * 128];   // W3^T hi
__device__ __align__(16) __nv_bfloat16 g_bl3[64 * 128];   // W3^T lo
__device__ __align__(16) float g_dis[MAXN];
__device__ __align__(16) int   g_cnt[MAXN];
__device__ __align__(16) int   g_offs[MAXN + 1];
__device__ __align__(16) int   g_slot[MAXE];       // within-node slot per edge
__device__ __align__(16) int   g_adj[MAXE];
__device__ __align__(16) int   g_bsum[128];
__device__ __align__(16) float g_sums[NG_GRAPHS * 64];
__device__ __align__(16) float g_gcnt[NG_GRAPHS];

// ---------------------------------------------------------------------------
// count in-degrees, 1 edge/thread (max parallelism hides ATOMG latency);
// atomic return value IS the slot. Also zeroes pooling buffers.
// ---------------------------------------------------------------------------
__global__ void count_kernel(const int* __restrict__ dst, int* cnt, int* slot,
                             float* sums, float* gcnt, int E) {
    int i = blockIdx.x * blockDim.x + threadIdx.x;
    if (i < E) slot[i] = atomicAdd(&cnt[dst[i]], 1);
    if (i < NG_GRAPHS * 64) sums[i] = 0.f;
    if (i < NG_GRAPHS) gcnt[i] = 0.f;
}

// ---------------------------------------------------------------------------
// tile scan: warp-shfl inclusive scan, 2 barriers (vs 20 in naive ladder)
// ---------------------------------------------------------------------------
__global__ __launch_bounds__(SCAN_B) void scan_block_kernel(
    const int* __restrict__ cnt, int* offs, int* bsum, int N) {
    __shared__ int wsum[32];
    int t = threadIdx.x;
    int warp = t >> 5;
    int lane = t & 31;
    int i = blockIdx.x * SCAN_B + t;
    int v = (i < N) ? cnt[i] : 0;
    int s = v;
#pragma unroll
    for (int o = 1; o < 32; o <<= 1) {
        int n = __shfl_up_sync(0xFFFFFFFFu, s, o);
        if (lane >= o) s += n;
    }
    if (lane == 31) wsum[warp] = s;
    __syncthreads();
    if (warp == 0) {
        int w = wsum[lane];
#pragma unroll
        for (int o = 1; o < 32; o <<= 1) {
            int n = __shfl_up_sync(0xFFFFFFFFu, w, o);
            if (lane >= o) w += n;
        }
        wsum[lane] = w;  // inclusive warp-total prefix
    }
    __syncthreads();
    int base = (warp > 0) ? wsum[warp - 1] : 0;
    int incl = s + base;
    if (i < N) offs[i] = incl - v;  // exclusive within tile
    if (t == SCAN_B - 1) bsum[blockIdx.x] = incl;  // tile total
}

// apply top-level scan (computed in-block over <=98 tile totals), finalize
// offs, compute dis and xd = x*dis, and self-clear cnt for the next call.
__global__ __launch_bounds__(256) void scan_add_kernel(
    int* offs, const int* __restrict__ bsum, int* cnt,
    const float* __restrict__ x, float* dis, float* xd, int N, int E) {
    __shared__ int base_sh;
    int tile = blockIdx.x >> 2;  // 256-thread block lies inside one 1024 tile
    if (threadIdx.x < 32) {
        int s = 0;
        for (int j = threadIdx.x; j < tile; j += 32) s += bsum[j];
#pragma unroll
        for (int o = 16; o; o >>= 1) s += __shfl_down_sync(0xFFFFFFFFu, s, o);
        if (threadIdx.x == 0) base_sh = s;
    }
    __syncthreads();
    int i = blockIdx.x * 256 + threadIdx.x;
    if (i < N) {
        offs[i] += base_sh;
        float d = rsqrtf((float)cnt[i] + 1.0f);  // +1 self loop
        cnt[i] = 0;                              // reset for next call
        dis[i] = d;
        float4 v;
        v.x = x[i * 3 + 0] * d;
        v.y = x[i * 3 + 1] * d;
        v.z = x[i * 3 + 2] * d;
        v.w = 0.f;
        *(float4*)(xd + i * 4) = v;
    }
    if (i == 0) offs[N] = E;
}

// ---------------------------------------------------------------------------
// fused: CSR fill (atomic-free scatter, 1 edge/thread) + W2/W3 prep
// ---------------------------------------------------------------------------
__global__ void fill_prep_kernel(const int* __restrict__ src, const int* __restrict__ dst,
                                 const int* __restrict__ offs, const int* __restrict__ slot,
                                 int* adj, int E,
                                 const float* __restrict__ W2, const float* __restrict__ W3,
                                 __nv_bfloat16* bh2, __nv_bfloat16* bl2,
                                 __nv_bfloat16* bh3, __nv_bfloat16* bl3) {
    int i = blockIdx.x * blockDim.x + threadIdx.x;
    if (i < E) {
        adj[__ldg(&offs[dst[i]]) + slot[i]] = src[i];
        return;
    }
    int k = i - E;
    if (k < 128 * 128) {
        int kk = k >> 7, n = k & 127;            // coalesced read of W2 row kk
        float w = W2[kk * 128 + n];
        __nv_bfloat16 hi = __float2bfloat16_rn(w);
        __nv_bfloat16 lo = __float2bfloat16_rn(w - __bfloat162float(hi));
        bh2[n * 128 + kk] = hi;                  // scattered store
        bl2[n * 128 + kk] = lo;
    } else if (k < 128 * 128 + 64 * 128) {
        int j = k - 128 * 128;
        int kk = j >> 6, n = j & 63;             // coalesced read of W3 row kk
        float w = W3[kk * 64 + n];
        __nv_bfloat16 hi = __float2bfloat16_rn(w);
        __nv_bfloat16 lo = __float2bfloat16_rn(w - __bfloat162float(hi));
        bh3[n * 128 + kk] = hi;
        bl3[n * 128 + kk] = lo;
    }
}

// ---------------------------------------------------------------------------
// layer-1 aggregation in 3-dim space: z[d] = xd[d] + sum_{s in adj(d)} xd[s]
// One THREAD per node (avg degree ~6 -> no idle lanes), unroll 4 (MLP).
// ---------------------------------------------------------------------------
__global__ __launch_bounds__(256) void agg3_kernel(
    const int* __restrict__ offs, const int* __restrict__ adj,
    const float* __restrict__ xd, float* __restrict__ z, int N) {
    int i = blockIdx.x * blockDim.x + threadIdx.x;
    if (i >= N) return;
    int beg = offs[i];
    int end = offs[i + 1];
    const float4* xv = (const float4*)xd;
    float4 s = __ldg(&xv[i]);  // self loop
    float sx = s.x, sy = s.y, sz = s.z;
    float ux = 0.f, uy = 0.f, uz = 0.f;
    int e = beg;
    for (; e + 4 <= end; e += 4) {
        int a0 = __ldg(&adj[e]);
        int a1 = __ldg(&adj[e + 1]);
        int a2 = __ldg(&adj[e + 2]);
        int a3 = __ldg(&adj[e + 3]);
        float4 v0 = __ldg(&xv[a0]);
        float4 v1 = __ldg(&xv[a1]);
        float4 v2 = __ldg(&xv[a2]);
        float4 v3 = __ldg(&xv[a3]);
        sx += v0.x + v2.x; sy += v0.y + v2.y; sz += v0.z + v2.z;
        ux += v1.x + v3.x; uy += v1.y + v3.y; uz += v1.z + v3.z;
    }
    for (; e < end; e++) {
        int a = __ldg(&adj[e]);
        float4 v = __ldg(&xv[a]);
        sx += v.x; sy += v.y; sz += v.z;
    }
    float4 o = make_float4(sx + ux, sy + uy, sz + uz, 0.f);
    *(float4*)(z + i * 4) = o;
}

#define LDH 72  // halfs per smem row (64 + 8 pad)

// ---------------------------------------------------------------------------
// FUSED layer-1 transform + layer-2 GEMM (tensor cores):
//   h1[n][c] = relu(dis[n]*(z[n]@W1[:,c]) + b1[c])  computed in A-staging,
//   out[n]   = fp16( (h1[n] @ W2) * dis[n] ),  bf16x3 split, fp32 accum.
// (scalar ws/bs smem layout: max 2-way conflicts, proven in R15)
// ---------------------------------------------------------------------------
__global__ __launch_bounds__(256) void gemm_l2_kernel(
    const float* __restrict__ z, const float* __restrict__ W1,
    const float* __restrict__ b1, const __nv_bfloat16* __restrict__ Bhg,
    const __nv_bfloat16* __restrict__ Blg, const float* __restrict__ dis,
    __half* __restrict__ out, int N) {
    extern __shared__ __align__(16) __nv_bfloat16 smh[];
    __nv_bfloat16* Ah = smh;             // 128 x LDH
    __nv_bfloat16* Al = Ah + 128 * LDH;  // 128 x LDH
    __nv_bfloat16* Bh = Al + 128 * LDH;  // 128 x LDH
    __nv_bfloat16* Bl = Bh + 128 * LDH;  // 128 x LDH
    __shared__ float ws[3 * 128];
    __shared__ float bs[128];

    const int tid = threadIdx.x;
    const int warp = tid >> 5;
    const int lane = tid & 31;
    const int g = lane >> 2;
    const int tg = lane & 3;
    const int n0 = blockIdx.x * 128;

    for (int i = tid; i < 384; i += 256) ws[i] = W1[i];
    for (int i = tid; i < 128; i += 256) bs[i] = b1[i];

    float acc[16][4];
#pragma unroll
    for (int i = 0; i < 16; i++) {
        acc[i][0] = acc[i][1] = acc[i][2] = acc[i][3] = 0.f;
    }

    for (int kc = 0; kc < 128; kc += 64) {
        __syncthreads();  // ws/bs ready (first iter); smem reuse (later iters)
        // stage A chunk [128 x 64]: h1 computed on the fly, bf16 hi/lo split
        for (int i = tid; i < 128 * 8; i += 256) {
            int r = i >> 3, c8 = i & 7;          // 8 cols per thread-iter
            int n = n0 + r;
            uint4 hu = make_uint4(0u, 0u, 0u, 0u);
            uint4 lu = make_uint4(0u, 0u, 0u, 0u);
            if (n < N) {
                float4 zv = *(const float4*)(z + n * 4);
                float d = dis[n];
                uint32_t* hw = (uint32_t*)&hu;
                uint32_t* lw = (uint32_t*)&lu;
#pragma unroll
                for (int q = 0; q < 4; q++) {
                    int c0 = kc + c8 * 8 + q * 2;
                    float o0 = fmaxf(fmaf(zv.x * ws[c0] + zv.y * ws[128 + c0] + zv.z * ws[256 + c0], d, bs[c0]), 0.f);
                    float o1 = fmaxf(fmaf(zv.x * ws[c0 + 1] + zv.y * ws[128 + c0 + 1] + zv.z * ws[256 + c0 + 1], d, bs[c0 + 1]), 0.f);
                    __nv_bfloat16 h0 = __float2bfloat16_rn(o0);
                    __nv_bfloat16 h1 = __float2bfloat16_rn(o1);
                    __nv_bfloat162 hh = {h0, h1};
                    __nv_bfloat162 ll = {__float2bfloat16_rn(o0 - __bfloat162float(h0)),
                                         __float2bfloat16_rn(o1 - __bfloat162float(h1))};
                    hw[q] = *(uint32_t*)&hh;
                    lw[q] = *(uint32_t*)&ll;
                }
            }
            *(uint4*)(Ah + r * LDH + c8 * 8) = hu;
            *(uint4*)(Al + r * LDH + c8 * 8) = lu;
        }
        // stage B chunk [128 x 64]
        for (int i = tid; i < 128 * 8; i += 256) {
            int r = i >> 3, c8 = i & 7;
            *(uint4*)(Bh + r * LDH + c8 * 8) = *(const uint4*)(Bhg + r * 128 + kc + c8 * 8);
            *(uint4*)(Bl + r * LDH + c8 * 8) = *(const uint4*)(Blg + r * 128 + kc + c8 * 8);
        }
        __syncthreads();

        const __nv_bfloat16* ar0 = Ah + (warp * 16 + g) * LDH + 2 * tg;
        const __nv_bfloat16* al0 = Al + (warp * 16 + g) * LDH + 2 * tg;
#pragma unroll
        for (int ks = 0; ks < 4; ks++) {
            const int ko = ks * 16;
            uint32_t ah0 = *(const uint32_t*)(ar0 + ko);
            uint32_t ah1 = *(const uint32_t*)(ar0 + 8 * LDH + ko);
            uint32_t ah2 = *(const uint32_t*)(ar0 + ko + 8);
            uint32_t ah3 = *(const uint32_t*)(ar0 + 8 * LDH + ko + 8);
            uint32_t aw0 = *(const uint32_t*)(al0 + ko);
            uint32_t aw1 = *(const uint32_t*)(al0 + 8 * LDH + ko);
            uint32_t aw2 = *(const uint32_t*)(al0 + ko + 8);
            uint32_t aw3 = *(const uint32_t*)(al0 + 8 * LDH + ko + 8);
#pragma unroll
            for (int nt = 0; nt < 16; nt++) {
                const __nv_bfloat16* bhr = Bh + (nt * 8 + g) * LDH + 2 * tg + ko;
                const __nv_bfloat16* blr = Bl + (nt * 8 + g) * LDH + 2 * tg + ko;
                uint32_t bh0 = *(const uint32_t*)bhr;
                uint32_t bh1 = *(const uint32_t*)(bhr + 8);
                uint32_t bl0 = *(const uint32_t*)blr;
                uint32_t bl1 = *(const uint32_t*)(blr + 8);
                asm volatile(
                    "mma.sync.aligned.m16n8k16.row.col.f32.bf16.bf16.f32 "
                    "{%0,%1,%2,%3}, {%4,%5,%6,%7}, {%8,%9}, {%0,%1,%2,%3};"
                    : "+f"(acc[nt][0]), "+f"(acc[nt][1]), "+f"(acc[nt][2]), "+f"(acc[nt][3])
                    : "r"(ah0), "r"(ah1), "r"(ah2), "r"(ah3), "r"(bh0), "r"(bh1));
                asm volatile(
                    "mma.sync.aligned.m16n8k16.row.col.f32.bf16.bf16.f32 "
                    "{%0,%1,%2,%3}, {%4,%5,%6,%7}, {%8,%9}, {%0,%1,%2,%3};"
                    : "+f"(acc[nt][0]), "+f"(acc[nt][1]), "+f"(acc[nt][2]), "+f"(acc[nt][3])
                    : "r"(aw0), "r"(aw1), "r"(aw2), "r"(aw3), "r"(bh0), "r"(bh1));
                asm volatile(
                    "mma.sync.aligned.m16n8k16.row.col.f32.bf16.bf16.f32 "
                    "{%0,%1,%2,%3}, {%4,%5,%6,%7}, {%8,%9}, {%0,%1,%2,%3};"
                    : "+f"(acc[nt][0]), "+f"(acc[nt][1]), "+f"(acc[nt][2]), "+f"(acc[nt][3])
                    : "r"(ah0), "r"(ah1), "r"(ah2), "r"(ah3), "r"(bl0), "r"(bl1));
            }
        }
    }

    int m0 = n0 + warp * 16 + g;
    int m1 = m0 + 8;
    float d0 = (m0 < N) ? dis[m0] : 0.f;
    float d1 = (m1 < N) ? dis[m1] : 0.f;
#pragma unroll
    for (int nt = 0; nt < 16; nt++) {
        if (m0 < N) {
            __half2 o = __floats2half2_rn(acc[nt][0] * d0, acc[nt][1] * d0);
            *(__half2*)(out + (size_t)m0 * 128 + nt * 8 + tg * 2) = o;
        }
        if (m1 < N) {
            __half2 o = __floats2half2_rn(acc[nt][2] * d1, acc[nt][3] * d1);
            *(__half2*)(out + (size_t)m1 * 128 + nt * 8 + tg * 2) = o;
        }
    }
}

// ---------------------------------------------------------------------------
// bf16x3 tensor-core GEMM (layer 3): A = fp16 h, F = 64.
// ---------------------------------------------------------------------------
template <int F>
__global__ __launch_bounds__(256) void gemm_mma_kernel(
    const __half* __restrict__ A, const __nv_bfloat16* __restrict__ Bhg,
    const __nv_bfloat16* __restrict__ Blg, const float* __restrict__ dis,
    __half* __restrict__ out, int N) {
    extern __shared__ __align__(16) __nv_bfloat16 smh[];
    __nv_bfloat16* Ah = smh;             // 128 x LDH
    __nv_bfloat16* Al = Ah + 128 * LDH;  // 128 x LDH
    __nv_bfloat16* Bh = Al + 128 * LDH;  // F x LDH
    __nv_bfloat16* Bl = Bh + F * LDH;    // F x LDH

    const int tid = threadIdx.x;
    const int warp = tid >> 5;
    const int lane = tid & 31;
    const int g = lane >> 2;
    const int tg = lane & 3;
    const int n0 = blockIdx.x * 128;

    constexpr int NT = F / 8;
    float acc[NT][4];
#pragma unroll
    for (int i = 0; i < NT; i++) {
        acc[i][0] = acc[i][1] = acc[i][2] = acc[i][3] = 0.f;
    }

    for (int kc = 0; kc < 128; kc += 64) {
        __syncthreads();
        for (int i = tid; i < 128 * 8; i += 256) {
            int r = i >> 3, c8 = i & 7;
            uint4 raw = make_uint4(0u, 0u, 0u, 0u);
            int n = n0 + r;
            if (n < N) raw = *(const uint4*)(A + (size_t)n * 128 + kc + c8 * 8);
            const __half2* hp = (const __half2*)&raw;
            uint4 hu, lu;
            uint32_t* hw = (uint32_t*)&hu;
            uint32_t* lw = (uint32_t*)&lu;
#pragma unroll
            for (int q = 0; q < 4; q++) {
                float2 fv = __half22float2(hp[q]);
                __nv_bfloat16 h0 = __float2bfloat16_rn(fv.x);
                __nv_bfloat16 h1 = __float2bfloat16_rn(fv.y);
                __nv_bfloat162 hh = {h0, h1};
                __nv_bfloat162 ll = {__float2bfloat16_rn(fv.x - __bfloat162float(h0)),
                                     __float2bfloat16_rn(fv.y - __bfloat162float(h1))};
                hw[q] = *(uint32_t*)&hh;
                lw[q] = *(uint32_t*)&ll;
            }
            *(uint4*)(Ah + r * LDH + c8 * 8) = hu;
            *(uint4*)(Al + r * LDH + c8 * 8) = lu;
        }
        for (int i = tid; i < F * 8; i += 256) {
            int r = i >> 3, c8 = i & 7;
            *(uint4*)(Bh + r * LDH + c8 * 8) = *(const uint4*)(Bhg + r * 128 + kc + c8 * 8);
            *(uint4*)(Bl + r * LDH + c8 * 8) = *(const uint4*)(Blg + r * 128 + kc + c8 * 8);
        }
        __syncthreads();

        const __nv_bfloat16* ar0 = Ah + (warp * 16 + g) * LDH + 2 * tg;
        const __nv_bfloat16* al0 = Al + (warp * 16 + g) * LDH + 2 * tg;
#pragma unroll
        for (int ks = 0; ks < 4; ks++) {
            const int ko = ks * 16;
            uint32_t ah0 = *(const uint32_t*)(ar0 + ko);
            uint32_t ah1 = *(const uint32_t*)(ar0 + 8 * LDH + ko);
            uint32_t ah2 = *(const uint32_t*)(ar0 + ko + 8);
            uint32_t ah3 = *(const uint32_t*)(ar0 + 8 * LDH + ko + 8);
            uint32_t aw0 = *(const uint32_t*)(al0 + ko);
            uint32_t aw1 = *(const uint32_t*)(al0 + 8 * LDH + ko);
            uint32_t aw2 = *(const uint32_t*)(al0 + ko + 8);
            uint32_t aw3 = *(const uint32_t*)(al0 + 8 * LDH + ko + 8);
#pragma unroll
            for (int nt = 0; nt < NT; nt++) {
                const __nv_bfloat16* bhr = Bh + (nt * 8 + g) * LDH + 2 * tg + ko;
                const __nv_bfloat16* blr = Bl + (nt * 8 + g) * LDH + 2 * tg + ko;
                uint32_t bh0 = *(const uint32_t*)bhr;
                uint32_t bh1 = *(const uint32_t*)(bhr + 8);
                uint32_t bl0 = *(const uint32_t*)blr;
                uint32_t bl1 = *(const uint32_t*)(blr + 8);
                asm volatile(
                    "mma.sync.aligned.m16n8k16.row.col.f32.bf16.bf16.f32 "
                    "{%0,%1,%2,%3}, {%4,%5,%6,%7}, {%8,%9}, {%0,%1,%2,%3};"
                    : "+f"(acc[nt][0]), "+f"(acc[nt][1]), "+f"(acc[nt][2]), "+f"(acc[nt][3])
                    : "r"(ah0), "r"(ah1), "r"(ah2), "r"(ah3), "r"(bh0), "r"(bh1));
                asm volatile(
                    "mma.sync.aligned.m16n8k16.row.col.f32.bf16.bf16.f32 "
                    "{%0,%1,%2,%3}, {%4,%5,%6,%7}, {%8,%9}, {%0,%1,%2,%3};"
                    : "+f"(acc[nt][0]), "+f"(acc[nt][1]), "+f"(acc[nt][2]), "+f"(acc[nt][3])
                    : "r"(aw0), "r"(aw1), "r"(aw2), "r"(aw3), "r"(bh0), "r"(bh1));
                asm volatile(
                    "mma.sync.aligned.m16n8k16.row.col.f32.bf16.bf16.f32 "
                    "{%0,%1,%2,%3}, {%4,%5,%6,%7}, {%8,%9}, {%0,%1,%2,%3};"
                    : "+f"(acc[nt][0]), "+f"(acc[nt][1]), "+f"(acc[nt][2]), "+f"(acc[nt][3])
                    : "r"(ah0), "r"(ah1), "r"(ah2), "r"(ah3), "r"(bl0), "r"(bl1));
            }
        }
    }

    int m0 = n0 + warp * 16 + g;
    int m1 = m0 + 8;
    float d0 = (m0 < N) ? dis[m0] : 0.f;
    float d1 = (m1 < N) ? dis[m1] : 0.f;
#pragma unroll
    for (int nt = 0; nt < NT; nt++) {
        if (m0 < N) {
            __half2 o = __floats2half2_rn(acc[nt][0] * d0, acc[nt][1] * d0);
            *(__half2*)(out + (size_t)m0 * F + nt * 8 + tg * 2) = o;
        }
        if (m1 < N) {
            __half2 o = __floats2half2_rn(acc[nt][2] * d1, acc[nt][3] * d1);
            *(__half2*)(out + (size_t)m1 * F + nt * 8 + tg * 2) = o;
        }
    }
}

// ---------------------------------------------------------------------------
// CSR gather + epilogue: h[d] = fp16(relu(dis[d]*(sum t[s] + t[d]) + b))
// One warp per dst node; fp16 payload, fp32 accumulation, fp16 h out.
// ---------------------------------------------------------------------------
template <int F>
__global__ __launch_bounds__(256) void gather_kernel(
    const int* __restrict__ offs, const int* __restrict__ adj,
    const __half* __restrict__ t, const float* __restrict__ dis,
    const float* __restrict__ b, __half* __restrict__ h, int N) {
    int node = (blockIdx.x * 256 + threadIdx.x) >> 5;
    int lane = threadIdx.x & 31;
    if (node >= N) return;
    int beg = offs[node];
    int end = offs[node + 1];
    float d = dis[node];
    if constexpr (F == 128) {
        const uint2* tv = (const uint2*)t;
        uint2 raw = __ldg(&tv[(size_t)node * 32 + lane]);  // self loop
        float2 f0 = __half22float2(*(__half2*)&raw.x);
        float2 f1 = __half22float2(*(__half2*)&raw.y);
        float s0 = f0.x, s1 = f0.y, s2 = f1.x, s3 = f1.y;
        float u0 = 0.f, u1 = 0.f, u2 = 0.f, u3 = 0.f;
        int e = beg;
        for (; e + 4 <= end; e += 4) {
            int a0 = __ldg(&adj[e]);
            int a1 = __ldg(&adj[e + 1]);
            int a2 = __ldg(&adj[e + 2]);
            int a3 = __ldg(&adj[e + 3]);
            uint2 r0 = __ldg(&tv[(size_t)a0 * 32 + lane]);
            uint2 r1 = __ldg(&tv[(size_t)a1 * 32 + lane]);
            uint2 r2 = __ldg(&tv[(size_t)a2 * 32 + lane]);
            uint2 r3 = __ldg(&tv[(size_t)a3 * 32 + lane]);
            float2 x0 = __half22float2(*(__half2*)&r0.x);
            float2 x1 = __half22float2(*(__half2*)&r0.y);
            float2 y0 = __half22float2(*(__half2*)&r1.x);
            float2 y1 = __half22float2(*(__half2*)&r1.y);
            float2 z0 = __half22float2(*(__half2*)&r2.x);
            float2 z1 = __half22float2(*(__half2*)&r2.y);
            float2 w0 = __half22float2(*(__half2*)&r3.x);
            float2 w1 = __half22float2(*(__half2*)&r3.y);
            s0 += x0.x + z0.x; s1 += x0.y + z0.y;
            s2 += x1.x + z1.x; s3 += x1.y + z1.y;
            u0 += y0.x + w0.x; u1 += y0.y + w0.y;
            u2 += y1.x + w1.x; u3 += y1.y + w1.y;
        }
        for (; e < end; e++) {
            int a = __ldg(&adj[e]);
            uint2 r0 = __ldg(&tv[(size_t)a * 32 + lane]);
            float2 x0 = __half22float2(*(__half2*)&r0.x);
            float2 x1 = __half22float2(*(__half2*)&r0.y);
            s0 += x0.x; s1 += x0.y; s2 += x1.x; s3 += x1.y;
        }
        float4 bv = __ldg(&((const float4*)b)[lane]);
        float o0 = fmaxf(fmaf(s0 + u0, d, bv.x), 0.f);
        float o1 = fmaxf(fmaf(s1 + u1, d, bv.y), 0.f);
        float o2 = fmaxf(fmaf(s2 + u2, d, bv.z), 0.f);
        float o3 = fmaxf(fmaf(s3 + u3, d, bv.w), 0.f);
        __half2 q0 = __floats2half2_rn(o0, o1);
        __half2 q1 = __floats2half2_rn(o2, o3);
        uint2 pk;
        pk.x = *(unsigned*)&q0;
        pk.y = *(unsigned*)&q1;
        ((uint2*)h)[(size_t)node * 32 + lane] = pk;
    } else {
        const uint32_t* tv = (const uint32_t*)t;
        uint32_t raw = __ldg(&tv[(size_t)node * 32 + lane]);  // self loop
        float2 f0 = __half22float2(*(__half2*)&raw);
        float s0 = f0.x, s1 = f0.y;
        float u0 = 0.f, u1 = 0.f;
        int e = beg;
        for (; e + 4 <= end; e += 4) {
            int a0 = __ldg(&adj[e]);
            int a1 = __ldg(&adj[e + 1]);
            int a2 = __ldg(&adj[e + 2]);
            int a3 = __ldg(&adj[e + 3]);
            uint32_t r0 = __ldg(&tv[(size_t)a0 * 32 + lane]);
            uint32_t r1 = __ldg(&tv[(size_t)a1 * 32 + lane]);
            uint32_t r2 = __ldg(&tv[(size_t)a2 * 32 + lane]);
            uint32_t r3 = __ldg(&tv[(size_t)a3 * 32 + lane]);
            float2 x0 = __half22float2(*(__half2*)&r0);
            float2 y0 = __half22float2(*(__half2*)&r1);
            float2 z0 = __half22float2(*(__half2*)&r2);
            float2 w0 = __half22float2(*(__half2*)&r3);
            s0 += x0.x + z0.x; s1 += x0.y + z0.y;
            u0 += y0.x + w0.x; u1 += y0.y + w0.y;
        }
        for (; e < end; e++) {
            int a = __ldg(&adj[e]);
            uint32_t r0 = __ldg(&tv[(size_t)a * 32 + lane]);
            float2 x0 = __half22float2(*(__half2*)&r0);
            s0 += x0.x; s1 += x0.y;
        }
        float2 bv = __ldg(&((const float2*)b)[lane]);
        float o0 = fmaxf(fmaf(s0 + u0, d, bv.x), 0.f);
        float o1 = fmaxf(fmaf(s1 + u1, d, bv.y), 0.f);
        __half2 q = __floats2half2_rn(o0, o1);
        ((uint32_t*)h)[(size_t)node * 32 + lane] = *(unsigned*)&q;
    }
}

// ---------------------------------------------------------------------------
// pooling: batch sorted -> segmented reduction. Block = 256 thr = 4 groups of
// 64 features; each group reduces a 64-node segment. fp16 h in, fp32 accum.
// ---------------------------------------------------------------------------
__global__ __launch_bounds__(256) void pool_kernel(
    const __half* __restrict__ h, const int* __restrict__ batch,
    float* __restrict__ sums, float* __restrict__ cnt, int N) {
    int grp = threadIdx.x >> 6;
    int f = threadIdx.x & 63;
    int start = blockIdx.x * 256 + grp * 64;
    if (start >= N) return;
    int end = min(start + 64, N);
    int g = batch[start];
    float s = 0.f, c = 0.f;
    for (int n = start; n < end; n++) {
        int bn = batch[n];
        if (bn != g) {
            atomicAdd(&sums[g * 64 + f], s);
            if (f == 0) atomicAdd(&cnt[g], c);
            s = 0.f; c = 0.f; g = bn;
        }
        s += __half2float(h[(size_t)n * 64 + f]);
        c += 1.f;
    }
    atomicAdd(&sums[g * 64 + f], s);
    if (f == 0) atomicAdd(&cnt[g], c);
}

__global__ void final_kernel(const float* __restrict__ sums, const float* __restrict__ cnt,
                             const float* __restrict__ Wl, const float* __restrict__ bl,
                             float* __restrict__ out) {
    int g = blockIdx.x * blockDim.x + threadIdx.x;
    if (g >= NG_GRAPHS) return;
    float c = fmaxf(cnt[g], 1.0f);
    float acc = 0.f;
#pragma unroll
    for (int f = 0; f < 64; f++) acc = fmaf(sums[g * 64 + f], Wl[f], acc);
    out[g] = acc / c + bl[0];
}

// ---------------------------------------------------------------------------
extern "C" void kernel_launch(void* const* d_in, const int* in_sizes, int n_in,
                              void* d_out, int out_size) {
    const float* x     = (const float*)d_in[0];
    const int*   ei    = (const int*)d_in[1];    // int32
    const int*   batch = (const int*)d_in[2];    // int32
    const float* W1 = (const float*)d_in[3];
    const float* b1 = (const float*)d_in[4];
    const float* W2 = (const float*)d_in[5];
    const float* b2 = (const float*)d_in[6];
    const float* W3 = (const float*)d_in[7];
    const float* b3 = (const float*)d_in[8];
    const float* Wl = (const float*)d_in[9];
    const float* bl = (const float*)d_in[10];
    float* out = (float*)d_out;

    const int N = in_sizes[0] / 3;
    const int E = in_sizes[1] / 2;
    const int* srcp = ei;
    const int* dstp = ei + E;

    float *xd, *z, *dis, *sums, *gcnt;
    __half *t, *h;
    __nv_bfloat16 *bh2, *bl2, *bh3, *bl3;
    int *cnt, *offs, *slot, *adj, *bsum;
    cudaGetSymbolAddress((void**)&t, g_t);
    cudaGetSymbolAddress((void**)&h, g_h);
    cudaGetSymbolAddress((void**)&xd, g_xd);
    cudaGetSymbolAddress((void**)&z, g_z);
    cudaGetSymbolAddress((void**)&bh2, g_bh2);
    cudaGetSymbolAddress((void**)&bl2, g_bl2);
    cudaGetSymbolAddress((void**)&bh3, g_bh3);
    cudaGetSymbolAddress((void**)&bl3, g_bl3);
    cudaGetSymbolAddress((void**)&dis, g_dis);
    cudaGetSymbolAddress((void**)&cnt, g_cnt);
    cudaGetSymbolAddress((void**)&offs, g_offs);
    cudaGetSymbolAddress((void**)&slot, g_slot);
    cudaGetSymbolAddress((void**)&adj, g_adj);
    cudaGetSymbolAddress((void**)&bsum, g_bsum);
    cudaGetSymbolAddress((void**)&sums, g_sums);
    cudaGetSymbolAddress((void**)&gcnt, g_gcnt);

    const int SMEM128 = (2 * 128 + 2 * 128) * LDH * 2;  // 73,728 B
    const int SMEM64  = (2 * 128 + 2 * 64) * LDH * 2;   // 55,296 B
    cudaFuncSetAttribute(gemm_l2_kernel,
                         cudaFuncAttributeMaxDynamicSharedMemorySize, SMEM128);
    cudaFuncSetAttribute(gemm_mma_kernel<64>,
                         cudaFuncAttributeMaxDynamicSharedMemorySize, SMEM64);

    const int nB = (N + 255) / 256;
    const int eB = (E + 255) / 256;
    const int NB_SCAN = (N + SCAN_B - 1) / SCAN_B;
    const int wB = (N * 32 + 255) / 256;      // warp-per-node grids
    const int gB = (N + 127) / 128;           // gemm grids
    const int fpB = (E + 128 * 128 + 64 * 128 + 255) / 256;

    // --- CSR build + prep (cnt zero at entry: zero-init call 1, ---
    // --- self-cleared by scan_add every call)                   ---
    count_kernel<<<eB, 256>>>(dstp, cnt, slot, sums, gcnt, E);
    scan_block_kernel<<<NB_SCAN, SCAN_B>>>(cnt, offs, bsum, N);
    scan_add_kernel<<<nB, 256>>>(offs, bsum, cnt, x, dis, xd, N, E);
    fill_prep_kernel<<<fpB, 256>>>(srcp, dstp, offs, slot, adj, E,
                                   W2, W3, bh2, bl2, bh3, bl3);

    // --- layer 1 aggregate (3-dim) ---
    agg3_kernel<<<nB, 256>>>(offs, adj, xd, z, N);

    // --- fused layer-1 transform + layer-2 GEMM ---
    gemm_l2_kernel<<<gB, 256, SMEM128>>>(z, W1, b1, bh2, bl2, dis, t, N);
    gather_kernel<128><<<wB, 256>>>(offs, adj, t, dis, b2, h, N);

    // --- layer 3 (128 -> 64) ---
    gemm_mma_kernel<64><<<gB, 256, SMEM64>>>(h, bh3, bl3, dis, t, N);
    gather_kernel<64><<<wB, 256>>>(offs, adj, t, dis, b3, h, N);

    // --- pooling + final linear ---
    pool_kernel<<<nB, 256>>>(h, batch, sums, gcnt, N);
    final_kernel<<<2, 256>>>(sums, gcnt, Wl, bl, out);
}